// round 5
// baseline (speedup 1.0000x reference)
#include <cuda_runtime.h>
#include <math.h>

#define Bsz  4
#define NN   32
#define EMB  512
#define FEAT 512
#define DOP  496
#define BD   (Bsz*DOP)   // 1984
#define KC   16          // split-K chunks in gemm

// output layout: concatenation of (X_raw, X_do, label, causal_graph, e, s)
#define OFF_XRAW 0
#define OFF_XDO  65536
#define OFF_LBL  32571392
#define OFF_CG   34603008
#define OFF_E    34607104
#define OFF_S    34611200

// scratch (no allocations allowed -> __device__ globals)
__device__ float    g_fU   [Bsz*NN*FEAT];
__device__ float    g_featD[Bsz*NN*FEAT];
__device__ float    g_part [KC*128*512];
__device__ float    g_attn [Bsz*NN*NN];
__device__ float    g_Wmain[Bsz*NN*NN];
__device__ unsigned g_posmask[Bsz*NN];
__device__ unsigned g_commonmask[Bsz*NN];

// packed fp32x2 FMA (SASS FFMA2) — 2x fp32 FMA throughput per issue slot.
__device__ __forceinline__ void ffma2(float2 &c, float2 a, float2 b) {
    asm("fma.rn.f32x2 %0, %1, %2, %0;"
        : "+l"(reinterpret_cast<unsigned long long&>(c))
        : "l"(reinterpret_cast<unsigned long long&>(a)),
          "l"(reinterpret_cast<unsigned long long&>(b)));
}

// ---------------------------------------------------------------------------
// C(128x512) = A(128x512) @ Bm(512x512), split-K into 16 chunks of 32.
// grid (8 ct, 4 rt, 16 kc), 256 threads. Tile 32x64 per block.
// mode 0: A = Aext (doc_sents_h) ; mode 1: A = g_fU
// ---------------------------------------------------------------------------
__global__ __launch_bounds__(256) void gemm_part_kernel(
    const float* __restrict__ Aext, const float* __restrict__ Bm, int mode)
{
    __shared__ float As[32][36];   // 144B rows: 16B-aligned
    __shared__ float Bs[32][64];
    const float* A = mode ? g_fU : Aext;
    int ct = blockIdx.x, rt = blockIdx.y, kc = blockIdx.z;
    int t = threadIdx.x;

    {   // A tile 32x32: 256 float4, 1 per thread
        int r = t >> 3, c4 = t & 7;
        float4 v = *reinterpret_cast<const float4*>(A + (rt*32 + r)*512 + kc*32 + c4*4);
        *reinterpret_cast<float4*>(&As[r][c4*4]) = v;
    }
    #pragma unroll
    for (int it = 0; it < 2; ++it) {   // B tile 32x64: 512 float4
        int l4 = t + 256*it;
        int kk = l4 >> 4, c4 = l4 & 15;
        *reinterpret_cast<float4*>(&Bs[kk][c4*4]) =
            *reinterpret_cast<const float4*>(Bm + (kc*32 + kk)*512 + ct*64 + c4*4);
    }
    __syncthreads();

    int c4 = t & 15, r2 = t >> 4;
    int i0 = r2*2, j0 = c4*4;
    float2 p00 = {0.f,0.f}, p01 = {0.f,0.f}, p10 = {0.f,0.f}, p11 = {0.f,0.f};
    #pragma unroll 8
    for (int kk = 0; kk < 32; ++kk) {
        float4 bv = *reinterpret_cast<const float4*>(&Bs[kk][j0]);
        float2 b01 = make_float2(bv.x, bv.y), b23 = make_float2(bv.z, bv.w);
        float x0 = As[i0][kk], x1 = As[i0+1][kk];
        ffma2(p00, make_float2(x0,x0), b01);
        ffma2(p01, make_float2(x0,x0), b23);
        ffma2(p10, make_float2(x1,x1), b01);
        ffma2(p11, make_float2(x1,x1), b23);
    }
    float* Cp = g_part + kc*65536;
    *reinterpret_cast<float4*>(Cp + (rt*32+i0  )*512 + ct*64 + j0) = make_float4(p00.x,p00.y,p01.x,p01.y);
    *reinterpret_cast<float4*>(Cp + (rt*32+i0+1)*512 + ct*64 + j0) = make_float4(p10.x,p10.y,p11.x,p11.y);
}

// reduce KC split-K partials into g_featD (float4 per thread)
__global__ void reduce16_kernel()
{
    int i4 = blockIdx.x*256 + threadIdx.x;   // 16384 float4 total
    const float4* P4 = reinterpret_cast<const float4*>(g_part);
    float4 a = P4[i4];
    #pragma unroll
    for (int c = 1; c < KC; ++c) {
        float4 v = P4[c*16384 + i4];
        a.x += v.x; a.y += v.y; a.z += v.z; a.w += v.w;
    }
    reinterpret_cast<float4*>(g_featD)[i4] = a;
}

// ---------------------------------------------------------------------------
// Encoder: per-batch block (4 blocks, 1024 threads). Dynamic smem = feat (64KB).
// Folds the split-K reduction of feat (reads g_part directly).
// ---------------------------------------------------------------------------
__global__ __launch_bounds__(1024) void enc_kernel(
    const float* __restrict__ adj, const float* __restrict__ asrc, const float* __restrict__ adst,
    const float* __restrict__ fce_w, const float* __restrict__ fce_b,
    const float* __restrict__ fcs_w, const float* __restrict__ fcs_b,
    const float* __restrict__ eps_main, float* __restrict__ out)
{
    extern __shared__ float Fs[];                  // 32 x 512
    __shared__ float At[32][33];
    __shared__ float Ms[32][33];
    __shared__ float ss[32], dd[32];
    __shared__ unsigned pm[32];
    int b = blockIdx.x;
    int t = threadIdx.x, w = t >> 5, lane = t & 31;

    const float4* P4 = reinterpret_cast<const float4*>(g_part);
    #pragma unroll
    for (int it = 0; it < 4; ++it) {
        int l4 = t + 1024*it;                  // float4 index within batch tile
        float4 a = P4[b*4096 + l4];
        #pragma unroll
        for (int c = 1; c < KC; ++c) {
            float4 v = P4[c*16384 + b*4096 + l4];
            a.x += v.x; a.y += v.y; a.z += v.z; a.w += v.w;
        }
        reinterpret_cast<float4*>(Fs)[l4] = a;
    }
    __syncthreads();

    {
        float s1 = 0.f, s2 = 0.f;
        #pragma unroll
        for (int c = 0; c < 16; ++c) {
            float f = Fs[w*512 + lane + 32*c];
            s1 += f * asrc[lane + 32*c];
            s2 += f * adst[lane + 32*c];
        }
        for (int o = 16; o; o >>= 1) {
            s1 += __shfl_xor_sync(0xffffffffu, s1, o);
            s2 += __shfl_xor_sync(0xffffffffu, s2, o);
        }
        if (lane == 0) { ss[w] = s1; dd[w] = s2; }
    }
    __syncthreads();

    {
        int i = w, j = lane;
        float sc = ss[i] + dd[j];
        float lr = sc > 0.f ? sc : 0.2f*sc;
        bool valid = (adj[b*1024 + i*32 + j] > 0.f) && (j < i);
        float m = valid ? lr : -1e9f;
        float mx = m;
        for (int o = 16; o; o >>= 1) mx = fmaxf(mx, __shfl_xor_sync(0xffffffffu, mx, o));
        float p = expf(m - mx);
        float sum = p;
        for (int o = 16; o; o >>= 1) sum += __shfl_xor_sync(0xffffffffu, sum, o);
        float av = valid ? p/sum : 0.f;
        At[i][j] = av;
        g_attn[b*1024 + i*32 + j] = av;
        out[OFF_CG + b*1024 + i*32 + j] = av;
        unsigned bal = __ballot_sync(0xffffffffu, av > 0.f);
        if (lane == 0) pm[i] = bal;
    }
    __syncthreads();

    {
        unsigned cm = __ballot_sync(0xffffffffu, (pm[w] & pm[lane]) != 0u);
        if (lane == 0) { g_posmask[b*32+w] = pm[w]; g_commonmask[b*32+w] = cm; }
    }
    __syncthreads();

    // inv(I - attn) forward substitution, column j register-resident
    if (w == 0) {
        int j = lane;
        float Mc[32];
        #pragma unroll
        for (int i = 0; i < 32; ++i) {
            float v = (i == j) ? 1.f : 0.f;
            #pragma unroll
            for (int k = 0; k < i; ++k) v += At[i][k] * Mc[k];
            Mc[i] = v;
            Ms[i][j] = v;
        }
    }
    __syncthreads();

    {
        float few = fce_w[0], feb = fce_b[0], fsw = fcs_w[0], fsb = fcs_b[0];
        int i = t >> 5, j = t & 31;
        float iv = Ms[i][j];
        float ev = few*iv + feb;
        float sv = fsw*iv + fsb;
        out[OFF_E + b*1024 + t] = ev;
        out[OFF_S + b*1024 + t] = sv;
        g_Wmain[b*1024 + t] = (iv == 0.f) ? 0.f : ev + expf(0.5f*sv)*eps_main[b*1024 + t];
    }

    // fU = relu(attn @ feat)
    {
        int jg = t & 127, rg = t >> 7;
        float2 acc[4][2];
        #pragma unroll
        for (int r = 0; r < 4; ++r) { acc[r][0] = make_float2(0.f,0.f); acc[r][1] = make_float2(0.f,0.f); }
        for (int k = 0; k < 32; ++k) {
            float4 f = reinterpret_cast<const float4*>(Fs + k*512)[jg];
            float2 f01 = make_float2(f.x,f.y), f23 = make_float2(f.z,f.w);
            #pragma unroll
            for (int r = 0; r < 4; ++r) {
                float wv = At[rg + 8*r][k];
                ffma2(acc[r][0], make_float2(wv,wv), f01);
                ffma2(acc[r][1], make_float2(wv,wv), f23);
            }
        }
        #pragma unroll
        for (int r = 0; r < 4; ++r) {
            int i = rg + 8*r;
            float4 o = make_float4(fmaxf(acc[r][0].x,0.f), fmaxf(acc[r][0].y,0.f),
                                   fmaxf(acc[r][1].x,0.f), fmaxf(acc[r][1].y,0.f));
            reinterpret_cast<float4*>(g_fU + b*16384 + i*512)[jg] = o;
        }
    }
}

// ---------------------------------------------------------------------------
// X_raw = relu(W_main @ featD). grid (8 coltiles, 4 batches), 256 threads.
// ---------------------------------------------------------------------------
__global__ __launch_bounds__(256) void xraw_kernel(float* __restrict__ out)
{
    __shared__ float Ws[32][33];
    __shared__ float Ft[32][64];
    int ct = blockIdx.x, b = blockIdx.y;
    int t = threadIdx.x;

    for (int e = t; e < 1024; e += 256) Ws[e>>5][e&31] = g_Wmain[b*1024 + e];
    #pragma unroll
    for (int it = 0; it < 2; ++it) {
        int l4 = t + 256*it;
        int k = l4 >> 4, c4 = l4 & 15;
        *reinterpret_cast<float4*>(&Ft[k][c4*4]) =
            *reinterpret_cast<const float4*>(g_featD + b*16384 + k*512 + ct*64 + c4*4);
    }
    __syncthreads();

    int jg = t & 15, rg = t >> 4;
    float2 a0[2] = {{0.f,0.f},{0.f,0.f}}, a1[2] = {{0.f,0.f},{0.f,0.f}};
    #pragma unroll 4
    for (int k = 0; k < 32; ++k) {
        float4 f = *reinterpret_cast<const float4*>(&Ft[k][jg*4]);
        float2 f01 = make_float2(f.x,f.y), f23 = make_float2(f.z,f.w);
        float w0 = Ws[rg][k], w1 = Ws[rg+16][k];
        ffma2(a0[0], make_float2(w0,w0), f01);
        ffma2(a0[1], make_float2(w0,w0), f23);
        ffma2(a1[0], make_float2(w1,w1), f01);
        ffma2(a1[1], make_float2(w1,w1), f23);
    }
    *reinterpret_cast<float4*>(out + OFF_XRAW + b*16384 + rg*512 + ct*64 + jg*4) =
        make_float4(fmaxf(a0[0].x,0.f),fmaxf(a0[0].y,0.f),fmaxf(a0[1].x,0.f),fmaxf(a0[1].y,0.f));
    *reinterpret_cast<float4*>(out + OFF_XRAW + b*16384 + (rg+16)*512 + ct*64 + jg*4) =
        make_float4(fmaxf(a1[0].x,0.f),fmaxf(a1[0].y,0.f),fmaxf(a1[1].x,0.f),fmaxf(a1[1].y,0.f));
}

// ---------------------------------------------------------------------------
// Main do-intervention kernel: 1984 blocks, 512 threads, 64KB dyn smem.
// Tile: 4 rows x 8 cols / thread; Wdo stored PERMUTED so each thread's 4 row
// weights for step k are one LDS.128 broadcast.
// ---------------------------------------------------------------------------
__global__ void __launch_bounds__(512, 2) do_kernel(
    const float* __restrict__ eps_do,
    const float* __restrict__ fce_w, const float* __restrict__ fce_b,
    const float* __restrict__ fcs_w, const float* __restrict__ fcs_b,
    float* __restrict__ out)
{
    extern __shared__ float Fsh[];                 // 32 x 512
    __shared__ float At[32][33];
    __shared__ float Minv[32][33];
    __shared__ float WdoP[32][36];                 // [k][(i&7)*4 + (i>>3)], 144B rows
    int bd = blockIdx.x;
    int b = bd / DOP, d = bd - b*DOP;
    int pa = 0, rem = d;
    while (rem >= NN-1-pa) { rem -= NN-1-pa; ++pa; }
    int pb = pa + 1 + rem;
    int t = threadIdx.x;

    // prefetch eps_do early: its DRAM latency hides behind the substitution
    float eps0 = eps_do[(size_t)bd*1024 + t];
    float eps1 = eps_do[(size_t)bd*1024 + t + 512];

    #pragma unroll
    for (int it = 0; it < 8; ++it) {
        int l4 = t + 512*it;
        reinterpret_cast<float4*>(Fsh)[l4] = reinterpret_cast<const float4*>(g_featD + b*16384)[l4];
    }
    for (int e = t; e < 1024; e += 512) At[e>>5][e&31] = g_attn[b*1024 + e];
    __syncthreads();

    // inv(I + Az) with rows pa,pb zeroed: column j register-resident.
    if (t < 32) {
        const int j = t;
        float Mc[32];
        #pragma unroll
        for (int i = 0; i < 32; ++i) {
            float v = (i == j) ? 1.f : 0.f;
            if (i != pa && i != pb) {
                float v2 = 0.f;
                #pragma unroll
                for (int k = 0; k + 1 < i; k += 2) {
                    v  -= At[i][k]   * Mc[k];
                    v2 -= At[i][k+1] * Mc[k+1];
                }
                if (i & 1) v -= At[i][i-1] * Mc[i-1];
                v += v2;
            }
            Mc[i] = v;
            Minv[i][j] = v;
        }
    }
    __syncthreads();

    float few = fce_w[0], feb = fce_b[0], fsw = fcs_w[0], fsb = fcs_b[0];
    #pragma unroll
    for (int it = 0; it < 2; ++it) {
        int e = t + it*512;
        int i = e >> 5, j = e & 31;
        float iv = Minv[i][j];
        float wv = 0.f;
        if (iv != 0.f)
            wv = few*iv + feb + expf(0.5f*(fsw*iv + fsb)) * (it ? eps1 : eps0);
        WdoP[j][((i & 7) << 2) | (i >> 3)] = wv;   // note: indexed [k=j][perm(i)]
        bool lower = j < i;
        bool c23 = lower && ((j==pa && i!=pb) || (j==pb && i!=pa));
        bool c4  = lower && (j!=pa) && (j!=pb) && (i!=pa) && (i!=pb);
        bool pos = (g_posmask[b*32+i]    >> j) & 1u;
        bool com = (g_commonmask[b*32+i] >> j) & 1u;
        bool lab = (i==j) || (c23 && pos) || (c4 && com);
        out[OFF_LBL + (size_t)bd*1024 + e] = lab ? 1.f : 0.f;
    }
    __syncthreads();

    // X_do = relu(Wdo @ Fsh): 4 rows (rg+8r) x 8 cols per thread.
    int jg = t & 63, rg = t >> 6;    // jg: 8-float col group; rg: 0..7
    float2 acc[4][4];
    #pragma unroll
    for (int r = 0; r < 4; ++r)
        #pragma unroll
        for (int c = 0; c < 4; ++c) acc[r][c] = make_float2(0.f,0.f);
    const float4* F4 = reinterpret_cast<const float4*>(Fsh);
    #pragma unroll 2
    for (int k = 0; k < 32; ++k) {
        float4 fa = F4[k*128 + jg*2];
        float4 fb = F4[k*128 + jg*2 + 1];
        float2 f0 = make_float2(fa.x,fa.y), f1 = make_float2(fa.z,fa.w);
        float2 f2 = make_float2(fb.x,fb.y), f3 = make_float2(fb.z,fb.w);
        float4 wv4 = *reinterpret_cast<const float4*>(&WdoP[k][rg*4]);  // rows rg, rg+8, rg+16, rg+24
        float wr[4] = {wv4.x, wv4.y, wv4.z, wv4.w};
        #pragma unroll
        for (int r = 0; r < 4; ++r) {
            float2 ww = make_float2(wr[r], wr[r]);
            ffma2(acc[r][0], ww, f0);
            ffma2(acc[r][1], ww, f1);
            ffma2(acc[r][2], ww, f2);
            ffma2(acc[r][3], ww, f3);
        }
    }
    float* ob = out + OFF_XDO + (size_t)bd*16384;
    #pragma unroll
    for (int r = 0; r < 4; ++r) {
        int i = rg + 8*r;
        float4* op = reinterpret_cast<float4*>(ob + i*512 + jg*8);
        op[0] = make_float4(fmaxf(acc[r][0].x,0.f), fmaxf(acc[r][0].y,0.f),
                            fmaxf(acc[r][1].x,0.f), fmaxf(acc[r][1].y,0.f));
        op[1] = make_float4(fmaxf(acc[r][2].x,0.f), fmaxf(acc[r][2].y,0.f),
                            fmaxf(acc[r][3].x,0.f), fmaxf(acc[r][3].y,0.f));
    }
}

// ---------------------------------------------------------------------------
extern "C" void kernel_launch(void* const* d_in, const int* in_sizes, int n_in,
                              void* d_out, int out_size)
{
    const float* h     = (const float*)d_in[0];
    const float* adj   = (const float*)d_in[1];
    const float* encWt = (const float*)d_in[3];
    const float* asrc  = (const float*)d_in[4];
    const float* adst  = (const float*)d_in[5];
    const float* decWt = (const float*)d_in[6];
    const float* fce_w = (const float*)d_in[7];
    const float* fce_b = (const float*)d_in[8];
    const float* fcs_w = (const float*)d_in[9];
    const float* fcs_b = (const float*)d_in[10];
    const float* eps_m = (const float*)d_in[11];
    const float* eps_d = (const float*)d_in[12];
    float* out = (float*)d_out;

    cudaFuncSetAttribute(enc_kernel, cudaFuncAttributeMaxDynamicSharedMemorySize, 65536);
    cudaFuncSetAttribute(do_kernel,  cudaFuncAttributeMaxDynamicSharedMemorySize, 65536);

    gemm_part_kernel<<<dim3(8,4,KC), 256>>>(h, encWt, 0);
    enc_kernel<<<4, 1024, 65536>>>(adj, asrc, adst, fce_w, fce_b, fcs_w, fcs_b, eps_m, out);
    gemm_part_kernel<<<dim3(8,4,KC), 256>>>(nullptr, decWt, 1);
    reduce16_kernel<<<64, 256>>>();
    xraw_kernel<<<dim3(8,4), 256>>>(out);
    do_kernel<<<BD, 512, 65536>>>(eps_d, fce_w, fce_b, fcs_w, fcs_b, out);
}

// round 6
// speedup vs baseline: 1.2427x; 1.2427x over previous
#include <cuda_runtime.h>
#include <math.h>

#define Bsz  4
#define NN   32
#define EMB  512
#define FEAT 512
#define DOP  496
#define BD   (Bsz*DOP)   // 1984

// output layout: concatenation of (X_raw, X_do, label, causal_graph, e, s)
#define OFF_XRAW 0
#define OFF_XDO  65536
#define OFF_LBL  32571392
#define OFF_CG   34603008
#define OFF_E    34607104
#define OFF_S    34611200

// scratch (no allocations allowed -> __device__ globals)
__device__ float    g_feat [Bsz*NN*FEAT];
__device__ float    g_fU   [Bsz*NN*FEAT];
__device__ float    g_featD[Bsz*NN*FEAT];
__device__ float    g_part [8*128*512];
__device__ float    g_attn [Bsz*NN*NN];
__device__ float    g_Wmain[Bsz*NN*NN];
__device__ unsigned g_posmask[Bsz*NN];
__device__ unsigned g_commonmask[Bsz*NN];

// packed fp32x2 FMA (SASS FFMA2) — 2x fp32 FMA throughput per issue slot.
__device__ __forceinline__ void ffma2(float2 &c, float2 a, float2 b) {
    asm("fma.rn.f32x2 %0, %1, %2, %0;"
        : "+l"(reinterpret_cast<unsigned long long&>(c))
        : "l"(reinterpret_cast<unsigned long long&>(a)),
          "l"(reinterpret_cast<unsigned long long&>(b)));
}

// ---------------------------------------------------------------------------
// C(128x512) = A(128x512) @ Bm(512x512), split-K into 8 chunks of 64.
// grid (8 ct, 4 rt, 8 kc), 256 threads. Tile 32x64 per block.
// mode 0: A = Aext (doc_sents_h) ; mode 1: A = g_fU
// ---------------------------------------------------------------------------
__global__ __launch_bounds__(256) void gemm_part_kernel(
    const float* __restrict__ Aext, const float* __restrict__ Bm, int mode)
{
    __shared__ float As[32][68];   // 272B rows: 16B-aligned
    __shared__ float Bs[64][64];
    const float* A = mode ? g_fU : Aext;
    int ct = blockIdx.x, rt = blockIdx.y, kc = blockIdx.z;
    int t = threadIdx.x;

    #pragma unroll
    for (int it = 0; it < 2; ++it) {
        int l4 = t + 256*it;                 // 512 float4 total (32x64)
        int r = l4 >> 4, c4 = l4 & 15;
        float4 v = *reinterpret_cast<const float4*>(A + (rt*32 + r)*512 + kc*64 + c4*4);
        *reinterpret_cast<float4*>(&As[r][c4*4]) = v;
    }
    #pragma unroll
    for (int it = 0; it < 4; ++it) {
        int l4 = t + 256*it;                 // 1024 float4 total (64x64)
        int kk = l4 >> 4, c4 = l4 & 15;
        *reinterpret_cast<float4*>(&Bs[kk][c4*4]) =
            *reinterpret_cast<const float4*>(Bm + (kc*64 + kk)*512 + ct*64 + c4*4);
    }
    __syncthreads();

    int c4 = t & 15, r2 = t >> 4;
    int i0 = r2*2, j0 = c4*4;
    float2 p00 = {0.f,0.f}, p01 = {0.f,0.f}, p10 = {0.f,0.f}, p11 = {0.f,0.f};
    #pragma unroll 8
    for (int kk = 0; kk < 64; ++kk) {
        float4 bv = *reinterpret_cast<const float4*>(&Bs[kk][j0]);
        float2 b01 = make_float2(bv.x, bv.y), b23 = make_float2(bv.z, bv.w);
        float x0 = As[i0][kk], x1 = As[i0+1][kk];
        ffma2(p00, make_float2(x0,x0), b01);
        ffma2(p01, make_float2(x0,x0), b23);
        ffma2(p10, make_float2(x1,x1), b01);
        ffma2(p11, make_float2(x1,x1), b23);
    }
    float* Cp = g_part + kc*65536;
    *reinterpret_cast<float4*>(Cp + (rt*32+i0  )*512 + ct*64 + j0) = make_float4(p00.x,p00.y,p01.x,p01.y);
    *reinterpret_cast<float4*>(Cp + (rt*32+i0+1)*512 + ct*64 + j0) = make_float4(p10.x,p10.y,p11.x,p11.y);
}

__global__ void reduce8_kernel(int mode)
{
    int i = blockIdx.x*256 + threadIdx.x;
    float v = 0.f;
    #pragma unroll
    for (int c = 0; c < 8; ++c) v += g_part[i + c*65536];
    (mode ? g_featD : g_feat)[i] = v;
}

// ---------------------------------------------------------------------------
// Encoder: per-batch block (4 blocks, 1024 threads). Dynamic smem = feat (64KB).
// ---------------------------------------------------------------------------
__global__ __launch_bounds__(1024) void enc_kernel(
    const float* __restrict__ adj, const float* __restrict__ asrc, const float* __restrict__ adst,
    const float* __restrict__ fce_w, const float* __restrict__ fce_b,
    const float* __restrict__ fcs_w, const float* __restrict__ fcs_b,
    const float* __restrict__ eps_main, float* __restrict__ out)
{
    extern __shared__ float Fs[];                  // 32 x 512
    __shared__ float At[32][33];
    __shared__ float Ms[32][33];
    __shared__ float ss[32], dd[32];
    __shared__ unsigned pm[32];
    int b = blockIdx.x;
    int t = threadIdx.x, w = t >> 5, lane = t & 31;

    #pragma unroll
    for (int it = 0; it < 4; ++it) {
        int l4 = t + 1024*it;
        reinterpret_cast<float4*>(Fs)[l4] = reinterpret_cast<const float4*>(g_feat + b*16384)[l4];
    }
    __syncthreads();

    {
        float s1 = 0.f, s2 = 0.f;
        #pragma unroll
        for (int c = 0; c < 16; ++c) {
            float f = Fs[w*512 + lane + 32*c];
            s1 += f * asrc[lane + 32*c];
            s2 += f * adst[lane + 32*c];
        }
        for (int o = 16; o; o >>= 1) {
            s1 += __shfl_xor_sync(0xffffffffu, s1, o);
            s2 += __shfl_xor_sync(0xffffffffu, s2, o);
        }
        if (lane == 0) { ss[w] = s1; dd[w] = s2; }
    }
    __syncthreads();

    {
        int i = w, j = lane;
        float sc = ss[i] + dd[j];
        float lr = sc > 0.f ? sc : 0.2f*sc;
        bool valid = (adj[b*1024 + i*32 + j] > 0.f) && (j < i);
        float m = valid ? lr : -1e9f;
        float mx = m;
        for (int o = 16; o; o >>= 1) mx = fmaxf(mx, __shfl_xor_sync(0xffffffffu, mx, o));
        float p = expf(m - mx);
        float sum = p;
        for (int o = 16; o; o >>= 1) sum += __shfl_xor_sync(0xffffffffu, sum, o);
        float av = valid ? p/sum : 0.f;
        At[i][j] = av;
        g_attn[b*1024 + i*32 + j] = av;
        out[OFF_CG + b*1024 + i*32 + j] = av;
        unsigned bal = __ballot_sync(0xffffffffu, av > 0.f);
        if (lane == 0) pm[i] = bal;
    }
    __syncthreads();

    {
        unsigned cm = __ballot_sync(0xffffffffu, (pm[w] & pm[lane]) != 0u);
        if (lane == 0) { g_posmask[b*32+w] = pm[w]; g_commonmask[b*32+w] = cm; }
    }
    __syncthreads();

    // inv(I - attn) forward substitution, column j register-resident
    if (w == 0) {
        int j = lane;
        float Mc[32];
        #pragma unroll
        for (int i = 0; i < 32; ++i) {
            float v = (i == j) ? 1.f : 0.f;
            #pragma unroll
            for (int k = 0; k < i; ++k) v += At[i][k] * Mc[k];
            Mc[i] = v;
            Ms[i][j] = v;
        }
    }
    __syncthreads();

    {
        float few = fce_w[0], feb = fce_b[0], fsw = fcs_w[0], fsb = fcs_b[0];
        int i = t >> 5, j = t & 31;
        float iv = Ms[i][j];
        float ev = few*iv + feb;
        float sv = fsw*iv + fsb;
        out[OFF_E + b*1024 + t] = ev;
        out[OFF_S + b*1024 + t] = sv;
        g_Wmain[b*1024 + t] = (iv == 0.f) ? 0.f : ev + expf(0.5f*sv)*eps_main[b*1024 + t];
    }

    // fU = relu(attn @ feat)
    {
        int jg = t & 127, rg = t >> 7;
        float2 acc[4][2];
        #pragma unroll
        for (int r = 0; r < 4; ++r) { acc[r][0] = make_float2(0.f,0.f); acc[r][1] = make_float2(0.f,0.f); }
        for (int k = 0; k < 32; ++k) {
            float4 f = reinterpret_cast<const float4*>(Fs + k*512)[jg];
            float2 f01 = make_float2(f.x,f.y), f23 = make_float2(f.z,f.w);
            #pragma unroll
            for (int r = 0; r < 4; ++r) {
                float wv = At[rg + 8*r][k];
                ffma2(acc[r][0], make_float2(wv,wv), f01);
                ffma2(acc[r][1], make_float2(wv,wv), f23);
            }
        }
        #pragma unroll
        for (int r = 0; r < 4; ++r) {
            int i = rg + 8*r;
            float4 o = make_float4(fmaxf(acc[r][0].x,0.f), fmaxf(acc[r][0].y,0.f),
                                   fmaxf(acc[r][1].x,0.f), fmaxf(acc[r][1].y,0.f));
            reinterpret_cast<float4*>(g_fU + b*16384 + i*512)[jg] = o;
        }
    }
}

// ---------------------------------------------------------------------------
// Main kernel: blocks [0, BD) = do-interventions; blocks [BD, BD+4) = X_raw.
// 512 threads, 64KB dyn smem (featD[b]).
// GEMM tile: 4 rows x 8 cols / thread. f-loads are lane-consecutive float4 at
// jg and jg+64 (both conflict-free); Wdo row-major, 4-k-chunk float4 broadcasts.
// ---------------------------------------------------------------------------
__global__ void __launch_bounds__(512, 2) do_kernel(
    const float* __restrict__ eps_do,
    const float* __restrict__ fce_w, const float* __restrict__ fce_b,
    const float* __restrict__ fcs_w, const float* __restrict__ fcs_b,
    float* __restrict__ out)
{
    extern __shared__ float Fsh[];                 // 32 x 512
    __shared__ float At[32][33];
    __shared__ float Minv[32][33];
    __shared__ float WdoS[32][36];                 // row-major, 144B rows (16B aligned)
    int bd = blockIdx.x;
    bool is_raw = (bd >= BD);
    int t = threadIdx.x;

    int b, pa = -1, pb = -1;
    if (is_raw) {
        b = bd - BD;
    } else {
        b = bd / DOP;
        int d = bd - b*DOP;
        int rem = d; pa = 0;
        while (rem >= NN-1-pa) { rem -= NN-1-pa; ++pa; }
        pb = pa + 1 + rem;
    }

    // prefetch eps_do early: DRAM latency hides behind the substitution
    float eps0 = 0.f, eps1 = 0.f;
    if (!is_raw) {
        eps0 = eps_do[(size_t)bd*1024 + t];
        eps1 = eps_do[(size_t)bd*1024 + t + 512];
    }

    #pragma unroll
    for (int it = 0; it < 8; ++it) {
        int l4 = t + 512*it;
        reinterpret_cast<float4*>(Fsh)[l4] = reinterpret_cast<const float4*>(g_featD + b*16384)[l4];
    }
    if (!is_raw)
        for (int e = t; e < 1024; e += 512) At[e>>5][e&31] = g_attn[b*1024 + e];
    __syncthreads();

    // inv(I + Az) with rows pa,pb zeroed: column j register-resident.
    if (!is_raw && t < 32) {
        const int j = t;
        float Mc[32];
        #pragma unroll
        for (int i = 0; i < 32; ++i) {
            float v = (i == j) ? 1.f : 0.f;
            if (i != pa && i != pb) {
                float v2 = 0.f;
                #pragma unroll
                for (int k = 0; k + 1 < i; k += 2) {
                    v  -= At[i][k]   * Mc[k];
                    v2 -= At[i][k+1] * Mc[k+1];
                }
                if (i & 1) v -= At[i][i-1] * Mc[i-1];
                v += v2;
            }
            Mc[i] = v;
            Minv[i][j] = v;
        }
    }
    __syncthreads();

    if (is_raw) {
        // W = precomputed g_Wmain; no label/eps
        #pragma unroll
        for (int it = 0; it < 2; ++it) {
            int e = t + it*512;
            WdoS[e>>5][e&31] = g_Wmain[b*1024 + e];
        }
    } else {
        float few = fce_w[0], feb = fce_b[0], fsw = fcs_w[0], fsb = fcs_b[0];
        #pragma unroll
        for (int it = 0; it < 2; ++it) {
            int e = t + it*512;
            int i = e >> 5, j = e & 31;
            float iv = Minv[i][j];
            float wv = 0.f;
            if (iv != 0.f)
                wv = few*iv + feb + expf(0.5f*(fsw*iv + fsb)) * (it ? eps1 : eps0);
            WdoS[i][j] = wv;
            bool lower = j < i;
            bool c23 = lower && ((j==pa && i!=pb) || (j==pb && i!=pa));
            bool c4  = lower && (j!=pa) && (j!=pb) && (i!=pa) && (i!=pb);
            bool pos = (g_posmask[b*32+i]    >> j) & 1u;
            bool com = (g_commonmask[b*32+i] >> j) & 1u;
            bool lab = (i==j) || (c23 && pos) || (c4 && com);
            out[OFF_LBL + (size_t)bd*1024 + e] = lab ? 1.f : 0.f;
        }
    }
    __syncthreads();

    // X = relu(W @ Fsh): rows rg+8r (r=0..3), cols jg & jg+64 (float4 each).
    int jg = t & 63, rg = t >> 6;    // rg uniform within a warp
    float2 acc[4][4];
    #pragma unroll
    for (int r = 0; r < 4; ++r)
        #pragma unroll
        for (int c = 0; c < 4; ++c) acc[r][c] = make_float2(0.f,0.f);
    const float4* F4 = reinterpret_cast<const float4*>(Fsh);
    for (int kc = 0; kc < 8; ++kc) {
        float4 w4[4];
        #pragma unroll
        for (int r = 0; r < 4; ++r)
            w4[r] = *reinterpret_cast<const float4*>(&WdoS[rg + 8*r][kc*4]);
        #pragma unroll
        for (int kk = 0; kk < 4; ++kk) {
            int k = kc*4 + kk;
            float4 fa = F4[k*128 + jg];
            float4 fb = F4[k*128 + 64 + jg];
            float2 f0 = make_float2(fa.x,fa.y), f1 = make_float2(fa.z,fa.w);
            float2 f2 = make_float2(fb.x,fb.y), f3 = make_float2(fb.z,fb.w);
            #pragma unroll
            for (int r = 0; r < 4; ++r) {
                float wv = (kk==0) ? w4[r].x : (kk==1) ? w4[r].y : (kk==2) ? w4[r].z : w4[r].w;
                float2 ww = make_float2(wv, wv);
                ffma2(acc[r][0], ww, f0);
                ffma2(acc[r][1], ww, f1);
                ffma2(acc[r][2], ww, f2);
                ffma2(acc[r][3], ww, f3);
            }
        }
    }
    float* ob = out + (is_raw ? (OFF_XRAW + (size_t)b*16384) : (OFF_XDO + (size_t)bd*16384));
    #pragma unroll
    for (int r = 0; r < 4; ++r) {
        int i = rg + 8*r;
        float4* op = reinterpret_cast<float4*>(ob + i*512);
        op[jg] = make_float4(fmaxf(acc[r][0].x,0.f), fmaxf(acc[r][0].y,0.f),
                             fmaxf(acc[r][1].x,0.f), fmaxf(acc[r][1].y,0.f));
        op[64 + jg] = make_float4(fmaxf(acc[r][2].x,0.f), fmaxf(acc[r][2].y,0.f),
                                  fmaxf(acc[r][3].x,0.f), fmaxf(acc[r][3].y,0.f));
    }
}

// ---------------------------------------------------------------------------
extern "C" void kernel_launch(void* const* d_in, const int* in_sizes, int n_in,
                              void* d_out, int out_size)
{
    const float* h     = (const float*)d_in[0];
    const float* adj   = (const float*)d_in[1];
    const float* encWt = (const float*)d_in[3];
    const float* asrc  = (const float*)d_in[4];
    const float* adst  = (const float*)d_in[5];
    const float* decWt = (const float*)d_in[6];
    const float* fce_w = (const float*)d_in[7];
    const float* fce_b = (const float*)d_in[8];
    const float* fcs_w = (const float*)d_in[9];
    const float* fcs_b = (const float*)d_in[10];
    const float* eps_m = (const float*)d_in[11];
    const float* eps_d = (const float*)d_in[12];
    float* out = (float*)d_out;

    cudaFuncSetAttribute(enc_kernel, cudaFuncAttributeMaxDynamicSharedMemorySize, 65536);
    cudaFuncSetAttribute(do_kernel,  cudaFuncAttributeMaxDynamicSharedMemorySize, 65536);

    gemm_part_kernel<<<dim3(8,4,8), 256>>>(h, encWt, 0);
    reduce8_kernel<<<256, 256>>>(0);
    enc_kernel<<<4, 1024, 65536>>>(adj, asrc, adst, fce_w, fce_b, fcs_w, fcs_b, eps_m, out);
    gemm_part_kernel<<<dim3(8,4,8), 256>>>(nullptr, decWt, 1);
    reduce8_kernel<<<256, 256>>>(1);
    do_kernel<<<BD + Bsz, 512, 65536>>>(eps_d, fce_w, fce_b, fcs_w, fcs_b, out);
}

// round 7
// speedup vs baseline: 1.3849x; 1.1145x over previous
#include <cuda_runtime.h>
#include <math.h>

#define Bsz  4
#define NN   32
#define EMB  512
#define FEAT 512
#define DOP  496
#define BD   (Bsz*DOP)   // 1984
#define KC   16          // split-K chunks in gemm
#define CPB  4           // do-cases per block
#define NDOB (BD/CPB)    // 496 do blocks

// output layout: concatenation of (X_raw, X_do, label, causal_graph, e, s)
#define OFF_XRAW 0
#define OFF_XDO  65536
#define OFF_LBL  32571392
#define OFF_CG   34603008
#define OFF_E    34607104
#define OFF_S    34611200

// scratch (no allocations allowed -> __device__ globals)
__device__ float    g_feat [Bsz*NN*FEAT];
__device__ float    g_fU   [Bsz*NN*FEAT];
__device__ float    g_featD[Bsz*NN*FEAT];
__device__ float    g_part [KC*128*512];
__device__ float    g_attn [Bsz*NN*NN];
__device__ float    g_Wmain[Bsz*NN*NN];
__device__ unsigned g_posmask[Bsz*NN];
__device__ unsigned g_commonmask[Bsz*NN];

// packed fp32x2 FMA (SASS FFMA2) — 2x fp32 FMA throughput per issue slot.
__device__ __forceinline__ void ffma2(float2 &c, float2 a, float2 b) {
    asm("fma.rn.f32x2 %0, %1, %2, %0;"
        : "+l"(reinterpret_cast<unsigned long long&>(c))
        : "l"(reinterpret_cast<unsigned long long&>(a)),
          "l"(reinterpret_cast<unsigned long long&>(b)));
}

// ---------------------------------------------------------------------------
// C(128x512) = A(128x512) @ Bm(512x512), split-K into 16 chunks of 32.
// grid (8 ct, 4 rt, 16 kc), 256 threads. Tile 32x64 per block.
// ---------------------------------------------------------------------------
__global__ __launch_bounds__(256) void gemm_part_kernel(
    const float* __restrict__ Aext, const float* __restrict__ Bm, int mode)
{
    __shared__ float As[32][36];   // 144B rows: 16B-aligned
    __shared__ float Bs[32][64];
    const float* A = mode ? g_fU : Aext;
    int ct = blockIdx.x, rt = blockIdx.y, kc = blockIdx.z;
    int t = threadIdx.x;

    {   // A tile 32x32: 256 float4
        int r = t >> 3, c4 = t & 7;
        float4 v = *reinterpret_cast<const float4*>(A + (rt*32 + r)*512 + kc*32 + c4*4);
        *reinterpret_cast<float4*>(&As[r][c4*4]) = v;
    }
    #pragma unroll
    for (int it = 0; it < 2; ++it) {   // B tile 32x64: 512 float4
        int l4 = t + 256*it;
        int kk = l4 >> 4, c4 = l4 & 15;
        *reinterpret_cast<float4*>(&Bs[kk][c4*4]) =
            *reinterpret_cast<const float4*>(Bm + (kc*32 + kk)*512 + ct*64 + c4*4);
    }
    __syncthreads();

    int c4 = t & 15, r2 = t >> 4;
    int i0 = r2*2, j0 = c4*4;
    float2 p00 = {0.f,0.f}, p01 = {0.f,0.f}, p10 = {0.f,0.f}, p11 = {0.f,0.f};
    #pragma unroll 8
    for (int kk = 0; kk < 32; ++kk) {
        float4 bv = *reinterpret_cast<const float4*>(&Bs[kk][j0]);
        float2 b01 = make_float2(bv.x, bv.y), b23 = make_float2(bv.z, bv.w);
        float x0 = As[i0][kk], x1 = As[i0+1][kk];
        ffma2(p00, make_float2(x0,x0), b01);
        ffma2(p01, make_float2(x0,x0), b23);
        ffma2(p10, make_float2(x1,x1), b01);
        ffma2(p11, make_float2(x1,x1), b23);
    }
    float* Cp = g_part + kc*65536;
    *reinterpret_cast<float4*>(Cp + (rt*32+i0  )*512 + ct*64 + j0) = make_float4(p00.x,p00.y,p01.x,p01.y);
    *reinterpret_cast<float4*>(Cp + (rt*32+i0+1)*512 + ct*64 + j0) = make_float4(p10.x,p10.y,p11.x,p11.y);
}

// reduce KC split-K partials. grid 128 x 128 threads (16384 = one float4 each).
__global__ void reduce16_kernel(int mode)
{
    int i4 = blockIdx.x*128 + threadIdx.x;
    const float4* P4 = reinterpret_cast<const float4*>(g_part);
    float4 a = P4[i4];
    #pragma unroll
    for (int c = 1; c < KC; ++c) {
        float4 v = P4[c*16384 + i4];
        a.x += v.x; a.y += v.y; a.z += v.z; a.w += v.w;
    }
    reinterpret_cast<float4*>(mode ? g_featD : g_feat)[i4] = a;
}

// ---------------------------------------------------------------------------
// Encoder: per-batch block (4 blocks, 1024 threads). Dynamic smem = feat (64KB).
// ---------------------------------------------------------------------------
__global__ __launch_bounds__(1024) void enc_kernel(
    const float* __restrict__ adj, const float* __restrict__ asrc, const float* __restrict__ adst,
    const float* __restrict__ fce_w, const float* __restrict__ fce_b,
    const float* __restrict__ fcs_w, const float* __restrict__ fcs_b,
    const float* __restrict__ eps_main, float* __restrict__ out)
{
    extern __shared__ float Fs[];                  // 32 x 512
    __shared__ float At[32][33];
    __shared__ float Ms[32][33];
    __shared__ float ss[32], dd[32];
    __shared__ unsigned pm[32];
    int b = blockIdx.x;
    int t = threadIdx.x, w = t >> 5, lane = t & 31;

    #pragma unroll
    for (int it = 0; it < 4; ++it) {
        int l4 = t + 1024*it;
        reinterpret_cast<float4*>(Fs)[l4] = reinterpret_cast<const float4*>(g_feat + b*16384)[l4];
    }
    __syncthreads();

    {
        float s1 = 0.f, s2 = 0.f;
        #pragma unroll
        for (int c = 0; c < 16; ++c) {
            float f = Fs[w*512 + lane + 32*c];
            s1 += f * asrc[lane + 32*c];
            s2 += f * adst[lane + 32*c];
        }
        for (int o = 16; o; o >>= 1) {
            s1 += __shfl_xor_sync(0xffffffffu, s1, o);
            s2 += __shfl_xor_sync(0xffffffffu, s2, o);
        }
        if (lane == 0) { ss[w] = s1; dd[w] = s2; }
    }
    __syncthreads();

    {
        int i = w, j = lane;
        float sc = ss[i] + dd[j];
        float lr = sc > 0.f ? sc : 0.2f*sc;
        bool valid = (adj[b*1024 + i*32 + j] > 0.f) && (j < i);
        float m = valid ? lr : -1e9f;
        float mx = m;
        for (int o = 16; o; o >>= 1) mx = fmaxf(mx, __shfl_xor_sync(0xffffffffu, mx, o));
        float p = expf(m - mx);
        float sum = p;
        for (int o = 16; o; o >>= 1) sum += __shfl_xor_sync(0xffffffffu, sum, o);
        float av = valid ? p/sum : 0.f;
        At[i][j] = av;
        g_attn[b*1024 + i*32 + j] = av;
        out[OFF_CG + b*1024 + i*32 + j] = av;
        unsigned bal = __ballot_sync(0xffffffffu, av > 0.f);
        if (lane == 0) pm[i] = bal;
    }
    __syncthreads();

    {
        unsigned cm = __ballot_sync(0xffffffffu, (pm[w] & pm[lane]) != 0u);
        if (lane == 0) { g_posmask[b*32+w] = pm[w]; g_commonmask[b*32+w] = cm; }
    }
    __syncthreads();

    if (w == 0) {
        int j = lane;
        float Mc[32];
        #pragma unroll
        for (int i = 0; i < 32; ++i) {
            float v = (i == j) ? 1.f : 0.f;
            #pragma unroll
            for (int k = 0; k < i; ++k) v += At[i][k] * Mc[k];
            Mc[i] = v;
            Ms[i][j] = v;
        }
    }
    __syncthreads();

    {
        float few = fce_w[0], feb = fce_b[0], fsw = fcs_w[0], fsb = fcs_b[0];
        int i = t >> 5, j = t & 31;
        float iv = Ms[i][j];
        float ev = few*iv + feb;
        float sv = fsw*iv + fsb;
        out[OFF_E + b*1024 + t] = ev;
        out[OFF_S + b*1024 + t] = sv;
        g_Wmain[b*1024 + t] = (iv == 0.f) ? 0.f : ev + expf(0.5f*sv)*eps_main[b*1024 + t];
    }

    // fU = relu(attn @ feat)
    {
        int jg = t & 127, rg = t >> 7;
        float2 acc[4][2];
        #pragma unroll
        for (int r = 0; r < 4; ++r) { acc[r][0] = make_float2(0.f,0.f); acc[r][1] = make_float2(0.f,0.f); }
        for (int k = 0; k < 32; ++k) {
            float4 f = reinterpret_cast<const float4*>(Fs + k*512)[jg];
            float2 f01 = make_float2(f.x,f.y), f23 = make_float2(f.z,f.w);
            #pragma unroll
            for (int r = 0; r < 4; ++r) {
                float wv = At[rg + 8*r][k];
                ffma2(acc[r][0], make_float2(wv,wv), f01);
                ffma2(acc[r][1], make_float2(wv,wv), f23);
            }
        }
        #pragma unroll
        for (int r = 0; r < 4; ++r) {
            int i = rg + 8*r;
            float4 o = make_float4(fmaxf(acc[r][0].x,0.f), fmaxf(acc[r][0].y,0.f),
                                   fmaxf(acc[r][1].x,0.f), fmaxf(acc[r][1].y,0.f));
            reinterpret_cast<float4*>(g_fU + b*16384 + i*512)[jg] = o;
        }
    }
}

// ---------------------------------------------------------------------------
// Main kernel: blocks [0, NDOB) handle 4 do-cases each (same batch b);
// blocks [NDOB, NDOB+4) handle X_raw for batch (blk - NDOB).
// 512 threads, 64KB dyn smem (featD[b] staged ONCE for all 4 cases).
// Substitutions for the 4 cases run in parallel in warps 0-3.
// ---------------------------------------------------------------------------
__global__ void __launch_bounds__(512, 2) do_kernel(
    const float* __restrict__ eps_do,
    const float* __restrict__ fce_w, const float* __restrict__ fce_b,
    const float* __restrict__ fcs_w, const float* __restrict__ fcs_b,
    float* __restrict__ out)
{
    extern __shared__ float Fsh[];                 // 32 x 512
    __shared__ float At[32][33];
    __shared__ float Minv[CPB][32][33];
    __shared__ float WdoS[CPB][32][36];            // row-major, 144B rows
    int g = blockIdx.x;
    bool is_raw = (g >= NDOB);
    int t = threadIdx.x;

    int b, bd0 = 0;
    int pa4[CPB], pb4[CPB];
    if (is_raw) {
        b = g - NDOB;
    } else {
        bd0 = g*CPB;
        b = bd0 / DOP;                             // 4 consecutive cases share b (496 % 4 == 0)
        #pragma unroll
        for (int c = 0; c < CPB; ++c) {
            int d = bd0 + c - b*DOP;
            int pa = 0, rem = d;
            while (rem >= NN-1-pa) { rem -= NN-1-pa; ++pa; }
            pa4[c] = pa; pb4[c] = pa + 1 + rem;
        }
    }

    // prefetch all eps up front: DRAM latency hides behind staging + substitution
    float eps[CPB][2];
    if (!is_raw) {
        #pragma unroll
        for (int c = 0; c < CPB; ++c) {
            eps[c][0] = eps_do[(size_t)(bd0+c)*1024 + t];
            eps[c][1] = eps_do[(size_t)(bd0+c)*1024 + t + 512];
        }
    }

    #pragma unroll
    for (int it = 0; it < 8; ++it) {
        int l4 = t + 512*it;
        reinterpret_cast<float4*>(Fsh)[l4] = reinterpret_cast<const float4*>(g_featD + b*16384)[l4];
    }
    if (!is_raw)
        for (int e = t; e < 1024; e += 512) At[e>>5][e&31] = g_attn[b*1024 + e];
    __syncthreads();

    // 4 parallel forward substitutions: warp c = case c, lane j = column j.
    if (!is_raw && t < 32*CPB) {
        const int c = t >> 5, j = t & 31;
        const int pa = pa4[c], pb = pb4[c];
        float Mc[32];
        #pragma unroll
        for (int i = 0; i < 32; ++i) {
            float v = (i == j) ? 1.f : 0.f;
            if (i != pa && i != pb) {
                float v2 = 0.f;
                #pragma unroll
                for (int k = 0; k + 1 < i; k += 2) {
                    v  -= At[i][k]   * Mc[k];
                    v2 -= At[i][k+1] * Mc[k+1];
                }
                if (i & 1) v -= At[i][i-1] * Mc[i-1];
                v += v2;
            }
            Mc[i] = v;
            Minv[c][i][j] = v;
        }
    }
    __syncthreads();

    if (is_raw) {
        #pragma unroll
        for (int it = 0; it < 2; ++it) {
            int e = t + it*512;
            WdoS[0][e>>5][e&31] = g_Wmain[b*1024 + e];
        }
    } else {
        float few = fce_w[0], feb = fce_b[0], fsw = fcs_w[0], fsb = fcs_b[0];
        unsigned posm_i0, comm_i0, posm_i1, comm_i1;
        {
            int i0 = t >> 5, i1 = (t + 512) >> 5;
            posm_i0 = g_posmask[b*32+i0]; comm_i0 = g_commonmask[b*32+i0];
            posm_i1 = g_posmask[b*32+i1]; comm_i1 = g_commonmask[b*32+i1];
        }
        #pragma unroll
        for (int c = 0; c < CPB; ++c) {
            int pa = pa4[c], pb = pb4[c];
            #pragma unroll
            for (int it = 0; it < 2; ++it) {
                int e = t + it*512;
                int i = e >> 5, j = e & 31;
                float iv = Minv[c][i][j];
                float wv = 0.f;
                if (iv != 0.f)
                    wv = few*iv + feb + expf(0.5f*(fsw*iv + fsb)) * eps[c][it];
                WdoS[c][i][j] = wv;
                bool lower = j < i;
                bool c23 = lower && ((j==pa && i!=pb) || (j==pb && i!=pa));
                bool c4  = lower && (j!=pa) && (j!=pb) && (i!=pa) && (i!=pb);
                bool pos = ((it ? posm_i1 : posm_i0) >> j) & 1u;
                bool com = ((it ? comm_i1 : comm_i0) >> j) & 1u;
                bool lab = (i==j) || (c23 && pos) || (c4 && com);
                out[OFF_LBL + (size_t)(bd0+c)*1024 + e] = lab ? 1.f : 0.f;
            }
        }
    }
    __syncthreads();

    // GEMM passes: X = relu(W @ Fsh), rows rg+8r (r=0..3), cols jg & jg+64.
    int jg = t & 63, rg = t >> 6;                  // rg uniform within a warp
    const float4* F4 = reinterpret_cast<const float4*>(Fsh);
    int ncase = is_raw ? 1 : CPB;
    for (int c = 0; c < ncase; ++c) {
        float2 acc[4][4];
        #pragma unroll
        for (int r = 0; r < 4; ++r)
            #pragma unroll
            for (int q = 0; q < 4; ++q) acc[r][q] = make_float2(0.f,0.f);
        for (int kc = 0; kc < 8; ++kc) {
            float4 w4[4];
            #pragma unroll
            for (int r = 0; r < 4; ++r)
                w4[r] = *reinterpret_cast<const float4*>(&WdoS[c][rg + 8*r][kc*4]);
            #pragma unroll
            for (int kk = 0; kk < 4; ++kk) {
                int k = kc*4 + kk;
                float4 fa = F4[k*128 + jg];
                float4 fb = F4[k*128 + 64 + jg];
                float2 f0 = make_float2(fa.x,fa.y), f1 = make_float2(fa.z,fa.w);
                float2 f2 = make_float2(fb.x,fb.y), f3 = make_float2(fb.z,fb.w);
                #pragma unroll
                for (int r = 0; r < 4; ++r) {
                    float wv = (kk==0) ? w4[r].x : (kk==1) ? w4[r].y : (kk==2) ? w4[r].z : w4[r].w;
                    float2 ww = make_float2(wv, wv);
                    ffma2(acc[r][0], ww, f0);
                    ffma2(acc[r][1], ww, f1);
                    ffma2(acc[r][2], ww, f2);
                    ffma2(acc[r][3], ww, f3);
                }
            }
        }
        float* ob = out + (is_raw ? (OFF_XRAW + (size_t)b*16384)
                                  : (OFF_XDO + (size_t)(bd0+c)*16384));
        #pragma unroll
        for (int r = 0; r < 4; ++r) {
            int i = rg + 8*r;
            float4* op = reinterpret_cast<float4*>(ob + i*512);
            op[jg] = make_float4(fmaxf(acc[r][0].x,0.f), fmaxf(acc[r][0].y,0.f),
                                 fmaxf(acc[r][1].x,0.f), fmaxf(acc[r][1].y,0.f));
            op[64 + jg] = make_float4(fmaxf(acc[r][2].x,0.f), fmaxf(acc[r][2].y,0.f),
                                      fmaxf(acc[r][3].x,0.f), fmaxf(acc[r][3].y,0.f));
        }
    }
}

// ---------------------------------------------------------------------------
extern "C" void kernel_launch(void* const* d_in, const int* in_sizes, int n_in,
                              void* d_out, int out_size)
{
    const float* h     = (const float*)d_in[0];
    const float* adj   = (const float*)d_in[1];
    const float* encWt = (const float*)d_in[3];
    const float* asrc  = (const float*)d_in[4];
    const float* adst  = (const float*)d_in[5];
    const float* decWt = (const float*)d_in[6];
    const float* fce_w = (const float*)d_in[7];
    const float* fce_b = (const float*)d_in[8];
    const float* fcs_w = (const float*)d_in[9];
    const float* fcs_b = (const float*)d_in[10];
    const float* eps_m = (const float*)d_in[11];
    const float* eps_d = (const float*)d_in[12];
    float* out = (float*)d_out;

    cudaFuncSetAttribute(enc_kernel, cudaFuncAttributeMaxDynamicSharedMemorySize, 65536);
    cudaFuncSetAttribute(do_kernel,  cudaFuncAttributeMaxDynamicSharedMemorySize, 65536);

    gemm_part_kernel<<<dim3(8,4,KC), 256>>>(h, encWt, 0);
    reduce16_kernel<<<128, 128>>>(0);
    enc_kernel<<<4, 1024, 65536>>>(adj, asrc, adst, fce_w, fce_b, fcs_w, fcs_b, eps_m, out);
    gemm_part_kernel<<<dim3(8,4,KC), 256>>>(nullptr, decWt, 1);
    reduce16_kernel<<<128, 128>>>(1);
    do_kernel<<<NDOB + Bsz, 512, 65536>>>(eps_d, fce_w, fce_b, fcs_w, fcs_b, out);
}

// round 8
// speedup vs baseline: 1.3887x; 1.0028x over previous
#include <cuda_runtime.h>
#include <math.h>

#define Bsz  4
#define NN   32
#define EMB  512
#define FEAT 512
#define DOP  496
#define BD   (Bsz*DOP)   // 1984
#define KC   16          // split-K chunks in gemm
#define CPB  4           // do-cases per block
#define NDOB (BD/CPB)    // 496 do blocks

// output layout: concatenation of (X_raw, X_do, label, causal_graph, e, s)
#define OFF_XRAW 0
#define OFF_XDO  65536
#define OFF_LBL  32571392
#define OFF_CG   34603008
#define OFF_E    34607104
#define OFF_S    34611200

// scratch (no allocations allowed -> __device__ globals)
__device__ float    g_feat [Bsz*NN*FEAT];
__device__ float    g_fU   [Bsz*NN*FEAT];
__device__ float    g_featD[Bsz*NN*FEAT];
__device__ float    g_part [KC*128*512];
__device__ float    g_attn [Bsz*NN*NN];
__device__ float    g_Wmain[Bsz*NN*NN];
__device__ unsigned g_posmask[Bsz*NN];
__device__ unsigned g_commonmask[Bsz*NN];

// packed fp32x2 FMA (SASS FFMA2) — 2x fp32 FMA throughput per issue slot.
__device__ __forceinline__ void ffma2(float2 &c, float2 a, float2 b) {
    asm("fma.rn.f32x2 %0, %1, %2, %0;"
        : "+l"(reinterpret_cast<unsigned long long&>(c))
        : "l"(reinterpret_cast<unsigned long long&>(a)),
          "l"(reinterpret_cast<unsigned long long&>(b)));
}

// ---------------------------------------------------------------------------
// C(128x512) = A(128x512) @ Bm(512x512), split-K into 16 chunks of 32.
// grid (8 ct, 4 rt, 16 kc), 256 threads. Tile 32x64 per block.
// ---------------------------------------------------------------------------
__global__ __launch_bounds__(256) void gemm_part_kernel(
    const float* __restrict__ Aext, const float* __restrict__ Bm, int mode)
{
    __shared__ float As[32][36];   // 144B rows: 16B-aligned
    __shared__ float Bs[32][64];
    const float* A = mode ? g_fU : Aext;
    int ct = blockIdx.x, rt = blockIdx.y, kc = blockIdx.z;
    int t = threadIdx.x;

    {   // A tile 32x32: 256 float4
        int r = t >> 3, c4 = t & 7;
        float4 v = *reinterpret_cast<const float4*>(A + (rt*32 + r)*512 + kc*32 + c4*4);
        *reinterpret_cast<float4*>(&As[r][c4*4]) = v;
    }
    #pragma unroll
    for (int it = 0; it < 2; ++it) {   // B tile 32x64: 512 float4
        int l4 = t + 256*it;
        int kk = l4 >> 4, c4 = l4 & 15;
        *reinterpret_cast<float4*>(&Bs[kk][c4*4]) =
            *reinterpret_cast<const float4*>(Bm + (kc*32 + kk)*512 + ct*64 + c4*4);
    }
    __syncthreads();

    int c4 = t & 15, r2 = t >> 4;
    int i0 = r2*2, j0 = c4*4;
    float2 p00 = {0.f,0.f}, p01 = {0.f,0.f}, p10 = {0.f,0.f}, p11 = {0.f,0.f};
    #pragma unroll 8
    for (int kk = 0; kk < 32; ++kk) {
        float4 bv = *reinterpret_cast<const float4*>(&Bs[kk][j0]);
        float2 b01 = make_float2(bv.x, bv.y), b23 = make_float2(bv.z, bv.w);
        float x0 = As[i0][kk], x1 = As[i0+1][kk];
        ffma2(p00, make_float2(x0,x0), b01);
        ffma2(p01, make_float2(x0,x0), b23);
        ffma2(p10, make_float2(x1,x1), b01);
        ffma2(p11, make_float2(x1,x1), b23);
    }
    float* Cp = g_part + kc*65536;
    *reinterpret_cast<float4*>(Cp + (rt*32+i0  )*512 + ct*64 + j0) = make_float4(p00.x,p00.y,p01.x,p01.y);
    *reinterpret_cast<float4*>(Cp + (rt*32+i0+1)*512 + ct*64 + j0) = make_float4(p10.x,p10.y,p11.x,p11.y);
}

// reduce KC split-K partials. grid 128 x 128 threads (16384 = one float4 each).
__global__ void reduce16_kernel(int mode)
{
    int i4 = blockIdx.x*128 + threadIdx.x;
    const float4* P4 = reinterpret_cast<const float4*>(g_part);
    float4 a = P4[i4];
    #pragma unroll
    for (int c = 1; c < KC; ++c) {
        float4 v = P4[c*16384 + i4];
        a.x += v.x; a.y += v.y; a.z += v.z; a.w += v.w;
    }
    reinterpret_cast<float4*>(mode ? g_featD : g_feat)[i4] = a;
}

// ---------------------------------------------------------------------------
// Encoder: per-batch block (4 blocks, 1024 threads). Dynamic smem = feat (64KB).
// ---------------------------------------------------------------------------
__global__ __launch_bounds__(1024) void enc_kernel(
    const float* __restrict__ adj, const float* __restrict__ asrc, const float* __restrict__ adst,
    const float* __restrict__ fce_w, const float* __restrict__ fce_b,
    const float* __restrict__ fcs_w, const float* __restrict__ fcs_b,
    const float* __restrict__ eps_main, float* __restrict__ out)
{
    extern __shared__ float Fs[];                  // 32 x 512
    __shared__ float At[32][33];
    __shared__ float Ms[32][33];
    __shared__ float ss[32], dd[32];
    __shared__ unsigned pm[32];
    int b = blockIdx.x;
    int t = threadIdx.x, w = t >> 5, lane = t & 31;

    #pragma unroll
    for (int it = 0; it < 4; ++it) {
        int l4 = t + 1024*it;
        reinterpret_cast<float4*>(Fs)[l4] = reinterpret_cast<const float4*>(g_feat + b*16384)[l4];
    }
    __syncthreads();

    {
        float s1 = 0.f, s2 = 0.f;
        #pragma unroll
        for (int c = 0; c < 16; ++c) {
            float f = Fs[w*512 + lane + 32*c];
            s1 += f * asrc[lane + 32*c];
            s2 += f * adst[lane + 32*c];
        }
        for (int o = 16; o; o >>= 1) {
            s1 += __shfl_xor_sync(0xffffffffu, s1, o);
            s2 += __shfl_xor_sync(0xffffffffu, s2, o);
        }
        if (lane == 0) { ss[w] = s1; dd[w] = s2; }
    }
    __syncthreads();

    {
        int i = w, j = lane;
        float sc = ss[i] + dd[j];
        float lr = sc > 0.f ? sc : 0.2f*sc;
        bool valid = (adj[b*1024 + i*32 + j] > 0.f) && (j < i);
        float m = valid ? lr : -1e9f;
        float mx = m;
        for (int o = 16; o; o >>= 1) mx = fmaxf(mx, __shfl_xor_sync(0xffffffffu, mx, o));
        float p = expf(m - mx);
        float sum = p;
        for (int o = 16; o; o >>= 1) sum += __shfl_xor_sync(0xffffffffu, sum, o);
        float av = valid ? p/sum : 0.f;
        At[i][j] = av;
        g_attn[b*1024 + i*32 + j] = av;
        out[OFF_CG + b*1024 + i*32 + j] = av;
        unsigned bal = __ballot_sync(0xffffffffu, av > 0.f);
        if (lane == 0) pm[i] = bal;
    }
    __syncthreads();

    {
        unsigned cm = __ballot_sync(0xffffffffu, (pm[w] & pm[lane]) != 0u);
        if (lane == 0) { g_posmask[b*32+w] = pm[w]; g_commonmask[b*32+w] = cm; }
    }
    __syncthreads();

    if (w == 0) {
        int j = lane;
        float Mc[32];
        #pragma unroll
        for (int i = 0; i < 32; ++i) {
            float v = (i == j) ? 1.f : 0.f;
            #pragma unroll
            for (int k = 0; k < i; ++k) v += At[i][k] * Mc[k];
            Mc[i] = v;
            Ms[i][j] = v;
        }
    }
    __syncthreads();

    {
        float few = fce_w[0], feb = fce_b[0], fsw = fcs_w[0], fsb = fcs_b[0];
        int i = t >> 5, j = t & 31;
        float iv = Ms[i][j];
        float ev = few*iv + feb;
        float sv = fsw*iv + fsb;
        out[OFF_E + b*1024 + t] = ev;
        out[OFF_S + b*1024 + t] = sv;
        g_Wmain[b*1024 + t] = (iv == 0.f) ? 0.f : ev + expf(0.5f*sv)*eps_main[b*1024 + t];
    }

    // fU = relu(attn @ feat)
    {
        int jg = t & 127, rg = t >> 7;
        float2 acc[4][2];
        #pragma unroll
        for (int r = 0; r < 4; ++r) { acc[r][0] = make_float2(0.f,0.f); acc[r][1] = make_float2(0.f,0.f); }
        for (int k = 0; k < 32; ++k) {
            float4 f = reinterpret_cast<const float4*>(Fs + k*512)[jg];
            float2 f01 = make_float2(f.x,f.y), f23 = make_float2(f.z,f.w);
            #pragma unroll
            for (int r = 0; r < 4; ++r) {
                float wv = At[rg + 8*r][k];
                ffma2(acc[r][0], make_float2(wv,wv), f01);
                ffma2(acc[r][1], make_float2(wv,wv), f23);
            }
        }
        #pragma unroll
        for (int r = 0; r < 4; ++r) {
            int i = rg + 8*r;
            float4 o = make_float4(fmaxf(acc[r][0].x,0.f), fmaxf(acc[r][0].y,0.f),
                                   fmaxf(acc[r][1].x,0.f), fmaxf(acc[r][1].y,0.f));
            reinterpret_cast<float4*>(g_fU + b*16384 + i*512)[jg] = o;
        }
    }
}

// ---------------------------------------------------------------------------
// Main kernel: blocks [0, NDOB) handle 4 do-cases each (same batch b);
// blocks [NDOB, NDOB+4) handle X_raw for batch (blk - NDOB).
// 512 threads, 64KB dyn smem (featD[b] staged ONCE for all 4 cases).
// Substitutions for the 4 cases run in parallel in warps 0-3.
// ---------------------------------------------------------------------------
__global__ void __launch_bounds__(512, 2) do_kernel(
    const float* __restrict__ eps_do,
    const float* __restrict__ fce_w, const float* __restrict__ fce_b,
    const float* __restrict__ fcs_w, const float* __restrict__ fcs_b,
    float* __restrict__ out)
{
    extern __shared__ float Fsh[];                 // 32 x 512
    __shared__ float At[32][33];
    __shared__ float Minv[CPB][32][33];
    __shared__ float WdoS[CPB][32][36];            // row-major, 144B rows
    int g = blockIdx.x;
    bool is_raw = (g >= NDOB);
    int t = threadIdx.x;

    int b, bd0 = 0;
    int pa4[CPB], pb4[CPB];
    if (is_raw) {
        b = g - NDOB;
    } else {
        bd0 = g*CPB;
        b = bd0 / DOP;                             // 4 consecutive cases share b (496 % 4 == 0)
        #pragma unroll
        for (int c = 0; c < CPB; ++c) {
            int d = bd0 + c - b*DOP;
            int pa = 0, rem = d;
            while (rem >= NN-1-pa) { rem -= NN-1-pa; ++pa; }
            pa4[c] = pa; pb4[c] = pa + 1 + rem;
        }
    }

    // prefetch all eps up front: DRAM latency hides behind staging + substitution
    float eps[CPB][2];
    if (!is_raw) {
        #pragma unroll
        for (int c = 0; c < CPB; ++c) {
            eps[c][0] = eps_do[(size_t)(bd0+c)*1024 + t];
            eps[c][1] = eps_do[(size_t)(bd0+c)*1024 + t + 512];
        }
    }

    #pragma unroll
    for (int it = 0; it < 8; ++it) {
        int l4 = t + 512*it;
        reinterpret_cast<float4*>(Fsh)[l4] = reinterpret_cast<const float4*>(g_featD + b*16384)[l4];
    }
    if (!is_raw)
        for (int e = t; e < 1024; e += 512) At[e>>5][e&31] = g_attn[b*1024 + e];
    __syncthreads();

    // 4 parallel forward substitutions: warp c = case c, lane j = column j.
    if (!is_raw && t < 32*CPB) {
        const int c = t >> 5, j = t & 31;
        const int pa = pa4[c], pb = pb4[c];
        float Mc[32];
        #pragma unroll
        for (int i = 0; i < 32; ++i) {
            float v = (i == j) ? 1.f : 0.f;
            if (i != pa && i != pb) {
                float v2 = 0.f;
                #pragma unroll
                for (int k = 0; k + 1 < i; k += 2) {
                    v  -= At[i][k]   * Mc[k];
                    v2 -= At[i][k+1] * Mc[k+1];
                }
                if (i & 1) v -= At[i][i-1] * Mc[i-1];
                v += v2;
            }
            Mc[i] = v;
            Minv[c][i][j] = v;
        }
    }
    __syncthreads();

    if (is_raw) {
        #pragma unroll
        for (int it = 0; it < 2; ++it) {
            int e = t + it*512;
            WdoS[0][e>>5][e&31] = g_Wmain[b*1024 + e];
        }
    } else {
        float few = fce_w[0], feb = fce_b[0], fsw = fcs_w[0], fsb = fcs_b[0];
        unsigned posm_i0, comm_i0, posm_i1, comm_i1;
        {
            int i0 = t >> 5, i1 = (t + 512) >> 5;
            posm_i0 = g_posmask[b*32+i0]; comm_i0 = g_commonmask[b*32+i0];
            posm_i1 = g_posmask[b*32+i1]; comm_i1 = g_commonmask[b*32+i1];
        }
        #pragma unroll
        for (int c = 0; c < CPB; ++c) {
            int pa = pa4[c], pb = pb4[c];
            #pragma unroll
            for (int it = 0; it < 2; ++it) {
                int e = t + it*512;
                int i = e >> 5, j = e & 31;
                float iv = Minv[c][i][j];
                float wv = 0.f;
                if (iv != 0.f)
                    wv = few*iv + feb + expf(0.5f*(fsw*iv + fsb)) * eps[c][it];
                WdoS[c][i][j] = wv;
                bool lower = j < i;
                bool c23 = lower && ((j==pa && i!=pb) || (j==pb && i!=pa));
                bool c4  = lower && (j!=pa) && (j!=pb) && (i!=pa) && (i!=pb);
                bool pos = ((it ? posm_i1 : posm_i0) >> j) & 1u;
                bool com = ((it ? comm_i1 : comm_i0) >> j) & 1u;
                bool lab = (i==j) || (c23 && pos) || (c4 && com);
                out[OFF_LBL + (size_t)(bd0+c)*1024 + e] = lab ? 1.f : 0.f;
            }
        }
    }
    __syncthreads();

    // GEMM passes: X = relu(W @ Fsh), rows rg+8r (r=0..3), cols jg & jg+64.
    int jg = t & 63, rg = t >> 6;                  // rg uniform within a warp
    const float4* F4 = reinterpret_cast<const float4*>(Fsh);
    int ncase = is_raw ? 1 : CPB;
    for (int c = 0; c < ncase; ++c) {
        float2 acc[4][4];
        #pragma unroll
        for (int r = 0; r < 4; ++r)
            #pragma unroll
            for (int q = 0; q < 4; ++q) acc[r][q] = make_float2(0.f,0.f);
        for (int kc = 0; kc < 8; ++kc) {
            float4 w4[4];
            #pragma unroll
            for (int r = 0; r < 4; ++r)
                w4[r] = *reinterpret_cast<const float4*>(&WdoS[c][rg + 8*r][kc*4]);
            #pragma unroll
            for (int kk = 0; kk < 4; ++kk) {
                int k = kc*4 + kk;
                float4 fa = F4[k*128 + jg];
                float4 fb = F4[k*128 + 64 + jg];
                float2 f0 = make_float2(fa.x,fa.y), f1 = make_float2(fa.z,fa.w);
                float2 f2 = make_float2(fb.x,fb.y), f3 = make_float2(fb.z,fb.w);
                #pragma unroll
                for (int r = 0; r < 4; ++r) {
                    float wv = (kk==0) ? w4[r].x : (kk==1) ? w4[r].y : (kk==2) ? w4[r].z : w4[r].w;
                    float2 ww = make_float2(wv, wv);
                    ffma2(acc[r][0], ww, f0);
                    ffma2(acc[r][1], ww, f1);
                    ffma2(acc[r][2], ww, f2);
                    ffma2(acc[r][3], ww, f3);
                }
            }
        }
        float* ob = out + (is_raw ? (OFF_XRAW + (size_t)b*16384)
                                  : (OFF_XDO + (size_t)(bd0+c)*16384));
        #pragma unroll
        for (int r = 0; r < 4; ++r) {
            int i = rg + 8*r;
            float4* op = reinterpret_cast<float4*>(ob + i*512);
            op[jg] = make_float4(fmaxf(acc[r][0].x,0.f), fmaxf(acc[r][0].y,0.f),
                                 fmaxf(acc[r][1].x,0.f), fmaxf(acc[r][1].y,0.f));
            op[64 + jg] = make_float4(fmaxf(acc[r][2].x,0.f), fmaxf(acc[r][2].y,0.f),
                                      fmaxf(acc[r][3].x,0.f), fmaxf(acc[r][3].y,0.f));
        }
    }
}

// ---------------------------------------------------------------------------
extern "C" void kernel_launch(void* const* d_in, const int* in_sizes, int n_in,
                              void* d_out, int out_size)
{
    const float* h     = (const float*)d_in[0];
    const float* adj   = (const float*)d_in[1];
    const float* encWt = (const float*)d_in[3];
    const float* asrc  = (const float*)d_in[4];
    const float* adst  = (const float*)d_in[5];
    const float* decWt = (const float*)d_in[6];
    const float* fce_w = (const float*)d_in[7];
    const float* fce_b = (const float*)d_in[8];
    const float* fcs_w = (const float*)d_in[9];
    const float* fcs_b = (const float*)d_in[10];
    const float* eps_m = (const float*)d_in[11];
    const float* eps_d = (const float*)d_in[12];
    float* out = (float*)d_out;

    cudaFuncSetAttribute(enc_kernel, cudaFuncAttributeMaxDynamicSharedMemorySize, 65536);
    cudaFuncSetAttribute(do_kernel,  cudaFuncAttributeMaxDynamicSharedMemorySize, 65536);

    gemm_part_kernel<<<dim3(8,4,KC), 256>>>(h, encWt, 0);
    reduce16_kernel<<<128, 128>>>(0);
    enc_kernel<<<4, 1024, 65536>>>(adj, asrc, adst, fce_w, fce_b, fcs_w, fcs_b, eps_m, out);
    gemm_part_kernel<<<dim3(8,4,KC), 256>>>(nullptr, decWt, 1);
    reduce16_kernel<<<128, 128>>>(1);
    do_kernel<<<NDOB + Bsz, 512, 65536>>>(eps_d, fce_w, fce_b, fcs_w, fcs_b, out);
}